// round 14
// baseline (speedup 1.0000x reference)
#include <cuda_runtime.h>
#include <cuda_bf16.h>
#include <cstdint>

#define BOX 256
#define KS 9
#define HALF (KS/2)
#define NP 20000
#define NB 16
#define NN 32
#define NL 3
#define LATENT 8

#define TDIM (BOX + KS - 1)              /* 264: padded in both x and y */
#define IMG_SIZE (NB*BOX*BOX)            /* 1048576 */
#define OFF_PD   (IMG_SIZE)              /* 1048576 */
#define OFF_RES  (OFF_PD + NB*NP*3)      /* 2008576 */
#define OFF_AC   (OFF_RES + NB*NP*3)     /* 2968576 */

__device__ float g_tmp[NB * TDIM * TDIM];   /* 4.46 MB scratch: point-mass buffer */
__device__ uint4 g_wb_hi[6*4*32];           /* packed B fragments (bf16 hi) */
__device__ uint4 g_wb_lo[6*4*32];           /* packed B fragments (bf16 lo) */
__device__ float g_camp[NB*NN];             /* per-batch latent contribution, amp head */
__device__ float g_cdef[NB*NN];             /* per-batch latent contribution, deform head */

__device__ __forceinline__ float tanh_fast(float x) {
    float e = __expf(2.f * x);
    return 1.f - __fdividef(2.f, e + 1.f);
}
__device__ __forceinline__ float sigmoid_fast(float x) {
    return __fdividef(1.f, 1.f + __expf(-x));
}
/* pack two fp32 into bf16x2: low half = lo arg, high half = hi arg */
__device__ __forceinline__ uint32_t pack_bf16(float lo, float hi) {
    uint32_t r;
    asm("cvt.rn.bf16x2.f32 %0, %1, %2;" : "=r"(r) : "f"(hi), "f"(lo));
    return r;
}
/* m16n8k16 bf16 MMA, fp32 accumulate in-place (sm_80+ PTX, arch-agnostic) */
__device__ __forceinline__ void mma16816(float* d, const uint32_t* a, uint32_t b0, uint32_t b1) {
    asm volatile(
        "mma.sync.aligned.m16n8k16.row.col.f32.bf16.bf16.f32 "
        "{%0,%1,%2,%3}, {%4,%5,%6,%7}, {%8,%9}, {%0,%1,%2,%3};"
        : "+f"(d[0]), "+f"(d[1]), "+f"(d[2]), "+f"(d[3])
        : "r"(a[0]), "r"(a[1]), "r"(a[2]), "r"(a[3]), "r"(b0), "r"(b1));
}

/* setup: zero scratch (all blocks) + pack fragments (blocks 0-5, one matrix each)
   + per-batch latent precompute (block 6). Pack overlaps the zero sweep. */
__global__ void setup_kernel(const float* __restrict__ z,
                             const float* __restrict__ linamp1_W,
                             const float* __restrict__ ampblock_W,
                             const float* __restrict__ deform_W,
                             const float* __restrict__ lin0_W)
{
    int gt = blockIdx.x * blockDim.x + threadIdx.x;
    if (gt < NB*TDIM*TDIM/4) ((float4*)g_tmp)[gt] = make_float4(0.f, 0.f, 0.f, 0.f);

    int tid = threadIdx.x;
    if (blockIdx.x < 6) {
        int l = blockIdx.x;
        if (tid < 128) {
            int i = l*128 + tid;
            int lane = tid & 31, nt = (tid >> 5) & 3;
            int n = 8*nt + (lane >> 2);
            int kb = 2*(lane & 3);
            const float* W = (l < 3) ? &ampblock_W[(l*NN + n)*NN] : &deform_W[((l-3)*NN + n)*NN];
            uint32_t hi[4], lo[4];
            int ks[4] = {kb, kb+8, kb+16, kb+24};
            #pragma unroll
            for (int q = 0; q < 4; q++) {
                float w0 = W[ks[q]], w1 = W[ks[q]+1];
                uint32_t h = pack_bf16(w0, w1);
                hi[q] = h;
                float h0 = __uint_as_float(h << 16);
                float h1 = __uint_as_float(h & 0xFFFF0000u);
                lo[q] = pack_bf16(w0 - h0, w1 - h1);
            }
            g_wb_hi[i] = make_uint4(hi[0], hi[1], hi[2], hi[3]);
            g_wb_lo[i] = make_uint4(lo[0], lo[1], lo[2], lo[3]);
        }
    } else if (blockIdx.x == 6) {
        for (int i = tid; i < NB*NN; i += 256) {
            int n = i & 31, b = i >> 5;
            g_camp[i] = linamp1_W[n*4 + 3] * z[b*LATENT + 7];
            float c = 0.f;
            #pragma unroll
            for (int j = 0; j < LATENT-1; j++) c += lin0_W[n*10 + 3 + j] * z[b*LATENT + j];
            g_cdef[i] = c;
        }
    }
}

/* One residual layer, dual-accumulator / interleaved-issue variant:
   d[nt] accumulates the three kt0 terms, e[nt] the three kt1 terms.
   Consecutive MMAs cycle nt (4-way independent); chains are 3 long, not 6. */
__device__ __forceinline__ void run_layer(float xf[4][4],
                                          const uint4* __restrict__ wb_hi,
                                          const uint4* __restrict__ wb_lo,
                                          const float* __restrict__ bias,
                                          int lane)
{
    uint32_t ah[8], al[8];
    #pragma unroll
    for (int kt = 0; kt < 2; kt++) {
        #pragma unroll
        for (int q = 0; q < 4; q++) {
            int nt = 2*kt + (q >> 1);
            int j0 = (q & 1) ? 2 : 0;
            float x0 = xf[nt][j0], x1 = xf[nt][j0+1];
            uint32_t h = pack_bf16(x0, x1);
            ah[kt*4+q] = h;
            float h0 = __uint_as_float(h << 16);
            float h1 = __uint_as_float(h & 0xFFFF0000u);
            al[kt*4+q] = pack_bf16(x0 - h0, x1 - h1);
        }
    }
    uint4 bh[4], bl[4];
    #pragma unroll
    for (int nt = 0; nt < 4; nt++) { bh[nt] = wb_hi[nt*32 + lane]; bl[nt] = wb_lo[nt*32 + lane]; }

    float d[4][4], e[4][4];
    #pragma unroll
    for (int nt = 0; nt < 4; nt++)
        #pragma unroll
        for (int j = 0; j < 4; j++) { d[nt][j] = 0.f; e[nt][j] = 0.f; }

    /* kt0 terms -> d (nt cycles fastest: consecutive MMAs independent) */
    #pragma unroll
    for (int nt = 0; nt < 4; nt++) mma16816(d[nt], ah,     bh[nt].x, bh[nt].y);   // hh kt0
    #pragma unroll
    for (int nt = 0; nt < 4; nt++) mma16816(e[nt], ah + 4, bh[nt].z, bh[nt].w);   // hh kt1
    #pragma unroll
    for (int nt = 0; nt < 4; nt++) mma16816(d[nt], al,     bh[nt].x, bh[nt].y);   // lh kt0
    #pragma unroll
    for (int nt = 0; nt < 4; nt++) mma16816(e[nt], al + 4, bh[nt].z, bh[nt].w);   // lh kt1
    #pragma unroll
    for (int nt = 0; nt < 4; nt++) mma16816(d[nt], ah,     bl[nt].x, bl[nt].y);   // hl kt0
    #pragma unroll
    for (int nt = 0; nt < 4; nt++) mma16816(e[nt], ah + 4, bl[nt].z, bl[nt].w);   // hl kt1

    int m2 = 2*(lane & 3);
    #pragma unroll
    for (int nt = 0; nt < 4; nt++) {
        float b0 = bias[8*nt + m2], b1 = bias[8*nt + m2 + 1];
        xf[nt][0] += fmaxf(d[nt][0] + e[nt][0] + b0, 0.f);
        xf[nt][1] += fmaxf(d[nt][1] + e[nt][1] + b1, 0.f);
        xf[nt][2] += fmaxf(d[nt][2] + e[nt][2] + b0, 0.f);
        xf[nt][3] += fmaxf(d[nt][3] + e[nt][3] + b1, 0.f);
    }
}

__global__ void __launch_bounds__(256) fused_decoder_kernel(
    const float* __restrict__ r,          // [16,3,3]
    const float* __restrict__ pos,        // [20000,3]
    const float* __restrict__ amp,        // [1]
    const float* __restrict__ linamp1_W,  // [32,4]
    const float* __restrict__ ampblock_b, // [3,32]
    const float* __restrict__ linamp2_W,  // [1,32]
    const float* __restrict__ linamp2_b,  // [1]
    const float* __restrict__ lin0_W,     // [32,10]
    const float* __restrict__ deform_b,   // [3,32]
    const float* __restrict__ lin1a_W,    // [3,32]
    const float* __restrict__ lin1b_W,    // [3,3]
    const int*   __restrict__ dptr,       // [1]
    float* __restrict__ out)
{
    __shared__ __align__(16) uint4 s_wb_hi[6*4*32];   // 12KB
    __shared__ __align__(16) uint4 s_wb_lo[6*4*32];   // 12KB
    __shared__ __align__(16) float s_bias[6*NN];
    __shared__ __align__(16) float4 s_la1p4[NN];
    __shared__ __align__(16) float4 s_l0p4[NN];
    __shared__ __align__(16) float s_camp[NB*NN];
    __shared__ __align__(16) float s_cdef[NB*NN];
    __shared__ __align__(16) float s_la2[NN];
    __shared__ __align__(16) float4 s_l1a4[NN];
    __shared__ float s_l1b[9];
    __shared__ float s_r[NB*9];
    __shared__ float s_la2b, s_amp;

    int tid = threadIdx.x;
    int dflag = *dptr;

    // ---- coalesced copy of pre-packed fragments + tables ----
    for (int i = tid; i < 6*4*32; i += 256) { s_wb_hi[i] = g_wb_hi[i]; s_wb_lo[i] = g_wb_lo[i]; }
    for (int i = tid; i < NB*NN; i += 256)  { s_camp[i] = g_camp[i]; s_cdef[i] = g_cdef[i]; }
    for (int i = tid; i < 3*NN; i += 256)   { s_bias[i] = ampblock_b[i]; s_bias[3*NN + i] = deform_b[i]; }
    for (int i = tid; i < NN; i += 256) {
        s_la1p4[i] = make_float4(linamp1_W[i*4+0], linamp1_W[i*4+1], linamp1_W[i*4+2], 0.f);
        s_l0p4[i]  = make_float4(lin0_W[i*10+0],  lin0_W[i*10+1],  lin0_W[i*10+2],  0.f);
        s_la2[i]   = linamp2_W[i];
        s_l1a4[i]  = make_float4(lin1a_W[0*NN+i], lin1a_W[1*NN+i], lin1a_W[2*NN+i], 0.f);
    }
    for (int i = tid; i < 9; i += 256)     s_l1b[i] = lin1b_W[i];
    for (int i = tid; i < NB*9; i += 256)  s_r[i]  = r[i];
    if (tid == 0) { s_la2b = linamp2_b[0]; s_amp = amp[0]; }
    __syncthreads();

    // ---- warp/lane geometry: each warp owns 16 consecutive points ----
    int lane = tid & 31;
    int g = lane >> 2;            // row group 0..7
    int m = lane & 3;             // col sub-owner
    int wbase = (blockIdx.x * 8 + (tid >> 5)) * 16;   // first point idx of warp
    int b = wbase / NP;                                // uniform per warp (16 | 20000)
    int p0 = wbase + g, p1 = wbase + g + 8;

    float P0x = pos[3*(p0 - b*NP) + 0], P0y = pos[3*(p0 - b*NP) + 1], P0z = pos[3*(p0 - b*NP) + 2];
    float P1x = pos[3*(p1 - b*NP) + 0], P1y = pos[3*(p1 - b*NP) + 1], P1z = pos[3*(p1 - b*NP) + 2];

    float xf[4][4];

    // ================= amplitude head =================
    #pragma unroll
    for (int nt = 0; nt < 4; nt++) {
        int c0 = 8*nt + 2*m;
        float4 w0 = s_la1p4[c0], w1 = s_la1p4[c0+1];
        float ca0 = s_camp[b*NN + c0], ca1 = s_camp[b*NN + c0 + 1];
        xf[nt][0] = ca0 + w0.x*P0x + w0.y*P0y + w0.z*P0z;
        xf[nt][1] = ca1 + w1.x*P0x + w1.y*P0y + w1.z*P0z;
        xf[nt][2] = ca0 + w0.x*P1x + w0.y*P1y + w0.z*P1z;
        xf[nt][3] = ca1 + w1.x*P1x + w1.y*P1y + w1.z*P1z;
    }
    #pragma unroll
    for (int l = 0; l < NL; l++)
        run_layer(xf, &s_wb_hi[l*4*32], &s_wb_lo[l*4*32], &s_bias[l*NN], lane);

    float sg = 0.f, sh = 0.f;   // amp final dot partials, rows g and g+8
    #pragma unroll
    for (int nt = 0; nt < 4; nt++) {
        int c0 = 8*nt + 2*m;
        float wa = s_la2[c0], wb = s_la2[c0+1];
        sg += xf[nt][0]*wa + xf[nt][1]*wb;
        sh += xf[nt][2]*wa + xf[nt][3]*wb;
    }
    sg += __shfl_xor_sync(0xFFFFFFFF, sg, 1); sg += __shfl_xor_sync(0xFFFFFFFF, sg, 2);
    sh += __shfl_xor_sync(0xFFFFFFFF, sh, 1); sh += __shfl_xor_sync(0xFFFFFFFF, sh, 2);

    // ================= deform head =================
    float t0g = 0.f, t1g = 0.f, t2g = 0.f, t0h = 0.f, t1h = 0.f, t2h = 0.f;
    if (dflag > 0) {
        #pragma unroll
        for (int nt = 0; nt < 4; nt++) {
            int c0 = 8*nt + 2*m;
            float4 w0 = s_l0p4[c0], w1 = s_l0p4[c0+1];
            float cd0 = s_cdef[b*NN + c0], cd1 = s_cdef[b*NN + c0 + 1];
            xf[nt][0] = cd0 + w0.x*P0x + w0.y*P0y + w0.z*P0z;
            xf[nt][1] = cd1 + w1.x*P0x + w1.y*P0y + w1.z*P0z;
            xf[nt][2] = cd0 + w0.x*P1x + w0.y*P1y + w0.z*P1z;
            xf[nt][3] = cd1 + w1.x*P1x + w1.y*P1y + w1.z*P1z;
        }
        #pragma unroll
        for (int l = 0; l < NL; l++)
            run_layer(xf, &s_wb_hi[(3+l)*4*32], &s_wb_lo[(3+l)*4*32], &s_bias[(3+l)*NN], lane);

        #pragma unroll
        for (int nt = 0; nt < 4; nt++) {
            int c0 = 8*nt + 2*m;
            float4 wa = s_l1a4[c0], wb = s_l1a4[c0+1];
            t0g += xf[nt][0]*wa.x + xf[nt][1]*wb.x;
            t1g += xf[nt][0]*wa.y + xf[nt][1]*wb.y;
            t2g += xf[nt][0]*wa.z + xf[nt][1]*wb.z;
            t0h += xf[nt][2]*wa.x + xf[nt][3]*wb.x;
            t1h += xf[nt][2]*wa.y + xf[nt][3]*wb.y;
            t2h += xf[nt][2]*wa.z + xf[nt][3]*wb.z;
        }
        t0g += __shfl_xor_sync(0xFFFFFFFF, t0g, 1); t0g += __shfl_xor_sync(0xFFFFFFFF, t0g, 2);
        t1g += __shfl_xor_sync(0xFFFFFFFF, t1g, 1); t1g += __shfl_xor_sync(0xFFFFFFFF, t1g, 2);
        t2g += __shfl_xor_sync(0xFFFFFFFF, t2g, 1); t2g += __shfl_xor_sync(0xFFFFFFFF, t2g, 2);
        t0h += __shfl_xor_sync(0xFFFFFFFF, t0h, 1); t0h += __shfl_xor_sync(0xFFFFFFFF, t0h, 2);
        t1h += __shfl_xor_sync(0xFFFFFFFF, t1h, 1); t1h += __shfl_xor_sync(0xFFFFFFFF, t1h, 2);
        t2h += __shfl_xor_sync(0xFFFFFFFF, t2h, 1); t2h += __shfl_xor_sync(0xFFFFFFFF, t2h, 2);
    }

    // ================= per-point epilogue (m=0 -> row g, m=1 -> row g+8) =================
    if (m < 2) {
        int idx = (m == 0) ? p0 : p1;
        float px = (m == 0) ? P0x : P1x;
        float py = (m == 0) ? P0y : P1y;
        float pz = (m == 0) ? P0z : P1z;
        float sacc = ((m == 0) ? sg : sh) + s_la2b;
        float amp_corr = sigmoid_fast(sacc);

        float res0 = 0.f, res1 = 0.f, res2 = 0.f;
        if (dflag > 0) {
            float t0 = (m == 0) ? t0g : t0h;
            float t1 = (m == 0) ? t1g : t1h;
            float t2 = (m == 0) ? t2g : t2h;
            t0 = tanh_fast(t0); t1 = tanh_fast(t1); t2 = tanh_fast(t2);
            res0 = t0*s_l1b[0] + t1*s_l1b[1] + t2*s_l1b[2];
            res1 = t0*s_l1b[3] + t1*s_l1b[4] + t2*s_l1b[5];
            res2 = t0*s_l1b[6] + t1*s_l1b[7] + t2*s_l1b[8];
        }
        float pd0 = px + res0, pd1 = py + res1, pd2 = pz + res2;

        out[OFF_AC + idx] = amp_corr;
        out[OFF_RES + 3*idx + 0] = res0;
        out[OFF_RES + 3*idx + 1] = res1;
        out[OFF_RES + 3*idx + 2] = res2;
        out[OFF_PD + 3*idx + 0] = pd0;
        out[OFF_PD + 3*idx + 1] = pd1;
        out[OFF_PD + 3*idx + 2] = pd2;

        const float* rb = &s_r[b*9];
        float proj0 = rb[0]*pd0 + rb[1]*pd1 + rb[2]*pd2;
        float proj1 = rb[3]*pd0 + rb[4]*pd1 + rb[5]*pd2;

        float A = s_amp * amp_corr;
        float fcx = rintf((proj0 + 0.5f) * (float)(BOX - 1));   // round-half-even = jnp.round
        float fcy = rintf((proj1 + 0.5f) * (float)(BOX - 1));

        if (fcx >= (float)(-HALF) && fcx <= (float)(BOX - 1 + HALF) &&
            fcy >= (float)(-HALF) && fcy <= (float)(BOX - 1 + HALF)) {
            int cx = (int)fcx, cy = (int)fcy;
            atomicAdd(&g_tmp[((size_t)b*TDIM + (cy + HALF))*TDIM + (cx + HALF)], A);
        }
    }
}

// Dense separable 9x9 conv over padded point-mass buffer.
// out[b][y][x] = sum_jy ky[jy] * sum_jx kx[jx] * tmp[b][y+8-jy][x+8-jx]
// where kx[j] = k2[4][j], ky[j] = k2[j][4]/k2[4][4]  (exact outer-product factorization)
__global__ void __launch_bounds__(256) conv_sep_kernel(const float* __restrict__ k2,
                                                       float* __restrict__ out)
{
    __shared__ float s_in[72][72];    // 64+8 halo in both dims
    __shared__ float s_mid[72][64];

    int bt  = blockIdx.x;             // 16 batches x 4x4 tiles = 256 blocks
    int b   = bt >> 4;
    int ty0 = ((bt >> 2) & 3) * 64;
    int tx0 = (bt & 3) * 64;
    int tid = threadIdx.x;

    float inv_c = 1.f / k2[HALF*KS + HALF];
    float kx[KS], ky[KS];
    #pragma unroll
    for (int j = 0; j < KS; j++) { kx[j] = k2[HALF*KS + j]; ky[j] = k2[j*KS + HALF] * inv_c; }

    const float* base = g_tmp + ((size_t)b*TDIM + ty0)*TDIM + tx0;
    for (int i = tid; i < 72*72; i += 256) {
        int rr = i / 72, cc = i % 72;
        s_in[rr][cc] = base[rr*TDIM + cc];
    }
    __syncthreads();

    for (int i = tid; i < 72*64; i += 256) {
        int rr = i >> 6, x = i & 63;
        float a = 0.f;
        #pragma unroll
        for (int jx = 0; jx < KS; jx++) a += kx[jx] * s_in[rr][x + 2*HALF - jx];
        s_mid[rr][x] = a;
    }
    __syncthreads();

    for (int i = tid; i < 64*64; i += 256) {
        int y = i >> 6, x = i & 63;
        float a = 0.f;
        #pragma unroll
        for (int jy = 0; jy < KS; jy++) a += ky[jy] * s_mid[y + 2*HALF - jy][x];
        out[((size_t)b*BOX + ty0 + y)*BOX + tx0 + x] = a;
    }
}

extern "C" void kernel_launch(void* const* d_in, const int* in_sizes, int n_in,
                              void* d_out, int out_size)
{
    const float* z          = (const float*)d_in[0];
    const float* r          = (const float*)d_in[1];
    const float* pos        = (const float*)d_in[2];
    const float* amp        = (const float*)d_in[3];
    const float* linamp1_W  = (const float*)d_in[4];
    const float* ampblock_W = (const float*)d_in[5];
    const float* ampblock_b = (const float*)d_in[6];
    const float* linamp2_W  = (const float*)d_in[7];
    const float* linamp2_b  = (const float*)d_in[8];
    const float* lin0_W     = (const float*)d_in[9];
    const float* deform_W   = (const float*)d_in[10];
    const float* deform_b   = (const float*)d_in[11];
    const float* lin1a_W    = (const float*)d_in[12];
    const float* lin1b_W    = (const float*)d_in[13];
    const float* k2         = (const float*)d_in[14];
    const int*   dptr       = (const int*)d_in[15];
    float* out = (float*)d_out;

    setup_kernel<<<(NB*TDIM*TDIM/4 + 255)/256, 256>>>(z, linamp1_W, ampblock_W, deform_W, lin0_W);
    fused_decoder_kernel<<<(NB*NP)/128, 256>>>(     // 2500 blocks: 8 warps x 16 points
        r, pos, amp, linamp1_W, ampblock_b, linamp2_W, linamp2_b,
        lin0_W, deform_b, lin1a_W, lin1b_W, dptr, out);
    conv_sep_kernel<<<256, 256>>>(k2, out);
}

// round 15
// speedup vs baseline: 1.0941x; 1.0941x over previous
#include <cuda_runtime.h>
#include <cuda_bf16.h>
#include <cstdint>

#define BOX 256
#define KS 9
#define HALF (KS/2)
#define NP 20000
#define NB 16
#define NN 32
#define NL 3
#define LATENT 8

#define TDIM (BOX + KS - 1)              /* 264: padded in both x and y */
#define IMG_SIZE (NB*BOX*BOX)            /* 1048576 */
#define OFF_PD   (IMG_SIZE)              /* 1048576 */
#define OFF_RES  (OFF_PD + NB*NP*3)      /* 2008576 */
#define OFF_AC   (OFF_RES + NB*NP*3)     /* 2968576 */

#define ZERO_N   (NB*TDIM*TDIM/4)        /* float4 count: 278784 */
#define ZERO_PER_T 2
#define ZERO_BLOCKS ((ZERO_N + 256*ZERO_PER_T - 1)/(256*ZERO_PER_T))   /* 545 */

__device__ float g_tmp[NB * TDIM * TDIM];   /* 4.46 MB scratch: point-mass buffer */
__device__ uint4 g_wb_hi[6*4*32];           /* packed B fragments (bf16 hi) */
__device__ uint4 g_wb_lo[6*4*32];           /* packed B fragments (bf16 lo) */
__device__ float g_camp[NB*NN];             /* per-batch latent contribution, amp head */
__device__ float g_cdef[NB*NN];             /* per-batch latent contribution, deform head */

__device__ __forceinline__ float tanh_fast(float x) {
    float e = __expf(2.f * x);
    return 1.f - __fdividef(2.f, e + 1.f);
}
__device__ __forceinline__ float sigmoid_fast(float x) {
    return __fdividef(1.f, 1.f + __expf(-x));
}
/* pack two fp32 into bf16x2: low half = lo arg, high half = hi arg */
__device__ __forceinline__ uint32_t pack_bf16(float lo, float hi) {
    uint32_t r;
    asm("cvt.rn.bf16x2.f32 %0, %1, %2;" : "=r"(r) : "f"(hi), "f"(lo));
    return r;
}
/* m16n8k16 bf16 MMA, fp32 accumulate in-place (sm_80+ PTX, arch-agnostic) */
__device__ __forceinline__ void mma16816(float* d, const uint32_t* a, uint32_t b0, uint32_t b1) {
    asm volatile(
        "mma.sync.aligned.m16n8k16.row.col.f32.bf16.bf16.f32 "
        "{%0,%1,%2,%3}, {%4,%5,%6,%7}, {%8,%9}, {%0,%1,%2,%3};"
        : "+f"(d[0]), "+f"(d[1]), "+f"(d[2]), "+f"(d[3])
        : "r"(a[0]), "r"(a[1]), "r"(a[2]), "r"(a[3]), "r"(b0), "r"(b1));
}

/* setup: zero scratch (2 float4/thread) + pack fragments (blocks 0-5) + latent precompute (block 6) */
__global__ void setup_kernel(const float* __restrict__ z,
                             const float* __restrict__ linamp1_W,
                             const float* __restrict__ ampblock_W,
                             const float* __restrict__ deform_W,
                             const float* __restrict__ lin0_W)
{
    int base = (blockIdx.x * blockDim.x + threadIdx.x) * ZERO_PER_T;
    float4 zf = make_float4(0.f, 0.f, 0.f, 0.f);
    #pragma unroll
    for (int q = 0; q < ZERO_PER_T; q++) {
        int i = base + q;
        if (i < ZERO_N) ((float4*)g_tmp)[i] = zf;
    }

    int tid = threadIdx.x;
    if (blockIdx.x < 6) {
        int l = blockIdx.x;
        if (tid < 128) {
            int i = l*128 + tid;
            int lane = tid & 31, nt = (tid >> 5) & 3;
            int n = 8*nt + (lane >> 2);
            int kb = 2*(lane & 3);
            const float* W = (l < 3) ? &ampblock_W[(l*NN + n)*NN] : &deform_W[((l-3)*NN + n)*NN];
            uint32_t hi[4], lo[4];
            int ks[4] = {kb, kb+8, kb+16, kb+24};
            #pragma unroll
            for (int q = 0; q < 4; q++) {
                float w0 = W[ks[q]], w1 = W[ks[q]+1];
                uint32_t h = pack_bf16(w0, w1);
                hi[q] = h;
                float h0 = __uint_as_float(h << 16);
                float h1 = __uint_as_float(h & 0xFFFF0000u);
                lo[q] = pack_bf16(w0 - h0, w1 - h1);
            }
            g_wb_hi[i] = make_uint4(hi[0], hi[1], hi[2], hi[3]);
            g_wb_lo[i] = make_uint4(lo[0], lo[1], lo[2], lo[3]);
        }
    } else if (blockIdx.x == 6) {
        for (int i = tid; i < NB*NN; i += 256) {
            int n = i & 31, b = i >> 5;
            g_camp[i] = linamp1_W[n*4 + 3] * z[b*LATENT + 7];
            float c = 0.f;
            #pragma unroll
            for (int j = 0; j < LATENT-1; j++) c += lin0_W[n*10 + 3 + j] * z[b*LATENT + j];
            g_cdef[i] = c;
        }
    }
}

/* One residual layer on fragment-resident activations xf[4][4] (proven 57.8us version) */
__device__ __forceinline__ void run_layer(float xf[4][4],
                                          const uint4* __restrict__ wb_hi,
                                          const uint4* __restrict__ wb_lo,
                                          const float* __restrict__ bias,
                                          int lane)
{
    uint32_t ah[8], al[8];
    #pragma unroll
    for (int kt = 0; kt < 2; kt++) {
        #pragma unroll
        for (int q = 0; q < 4; q++) {
            int nt = 2*kt + (q >> 1);
            int j0 = (q & 1) ? 2 : 0;
            float x0 = xf[nt][j0], x1 = xf[nt][j0+1];
            uint32_t h = pack_bf16(x0, x1);
            ah[kt*4+q] = h;
            float h0 = __uint_as_float(h << 16);
            float h1 = __uint_as_float(h & 0xFFFF0000u);
            al[kt*4+q] = pack_bf16(x0 - h0, x1 - h1);
        }
    }
    float d[4][4];
    #pragma unroll
    for (int nt = 0; nt < 4; nt++)
        #pragma unroll
        for (int j = 0; j < 4; j++) d[nt][j] = 0.f;

    #pragma unroll
    for (int nt = 0; nt < 4; nt++) {
        uint4 bh = wb_hi[nt*32 + lane];
        uint4 bl = wb_lo[nt*32 + lane];
        mma16816(d[nt], ah,     bh.x, bh.y);   // hi*hi kt0
        mma16816(d[nt], ah + 4, bh.z, bh.w);   // hi*hi kt1
        mma16816(d[nt], al,     bh.x, bh.y);   // lo*hi kt0
        mma16816(d[nt], al + 4, bh.z, bh.w);   // lo*hi kt1
        mma16816(d[nt], ah,     bl.x, bl.y);   // hi*lo kt0
        mma16816(d[nt], ah + 4, bl.z, bl.w);   // hi*lo kt1
    }
    int m2 = 2*(lane & 3);
    #pragma unroll
    for (int nt = 0; nt < 4; nt++) {
        float b0 = bias[8*nt + m2], b1 = bias[8*nt + m2 + 1];
        xf[nt][0] += fmaxf(d[nt][0] + b0, 0.f);
        xf[nt][1] += fmaxf(d[nt][1] + b1, 0.f);
        xf[nt][2] += fmaxf(d[nt][2] + b0, 0.f);
        xf[nt][3] += fmaxf(d[nt][3] + b1, 0.f);
    }
}

__global__ void __launch_bounds__(256) fused_decoder_kernel(
    const float* __restrict__ r,          // [16,3,3]
    const float* __restrict__ pos,        // [20000,3]
    const float* __restrict__ amp,        // [1]
    const float* __restrict__ linamp1_W,  // [32,4]
    const float* __restrict__ ampblock_b, // [3,32]
    const float* __restrict__ linamp2_W,  // [1,32]
    const float* __restrict__ linamp2_b,  // [1]
    const float* __restrict__ lin0_W,     // [32,10]
    const float* __restrict__ deform_b,   // [3,32]
    const float* __restrict__ lin1a_W,    // [3,32]
    const float* __restrict__ lin1b_W,    // [3,3]
    const int*   __restrict__ dptr,       // [1]
    float* __restrict__ out)
{
    __shared__ __align__(16) uint4 s_wb_hi[6*4*32];   // 12KB
    __shared__ __align__(16) uint4 s_wb_lo[6*4*32];   // 12KB
    __shared__ __align__(16) float s_bias[6*NN];
    __shared__ __align__(16) float4 s_la1p4[NN];
    __shared__ __align__(16) float4 s_l0p4[NN];
    __shared__ __align__(16) float s_camp[NB*NN];
    __shared__ __align__(16) float s_cdef[NB*NN];
    __shared__ __align__(16) float s_la2[NN];
    __shared__ __align__(16) float4 s_l1a4[NN];
    __shared__ float s_l1b[9];
    __shared__ float s_r[NB*9];
    __shared__ float s_la2b, s_amp;

    int tid = threadIdx.x;
    int dflag = *dptr;

    // ---- coalesced copy of pre-packed fragments + tables ----
    for (int i = tid; i < 6*4*32; i += 256) { s_wb_hi[i] = g_wb_hi[i]; s_wb_lo[i] = g_wb_lo[i]; }
    for (int i = tid; i < NB*NN; i += 256)  { s_camp[i] = g_camp[i]; s_cdef[i] = g_cdef[i]; }
    for (int i = tid; i < 3*NN; i += 256)   { s_bias[i] = ampblock_b[i]; s_bias[3*NN + i] = deform_b[i]; }
    for (int i = tid; i < NN; i += 256) {
        s_la1p4[i] = make_float4(linamp1_W[i*4+0], linamp1_W[i*4+1], linamp1_W[i*4+2], 0.f);
        s_l0p4[i]  = make_float4(lin0_W[i*10+0],  lin0_W[i*10+1],  lin0_W[i*10+2],  0.f);
        s_la2[i]   = linamp2_W[i];
        s_l1a4[i]  = make_float4(lin1a_W[0*NN+i], lin1a_W[1*NN+i], lin1a_W[2*NN+i], 0.f);
    }
    for (int i = tid; i < 9; i += 256)     s_l1b[i] = lin1b_W[i];
    for (int i = tid; i < NB*9; i += 256)  s_r[i]  = r[i];
    if (tid == 0) { s_la2b = linamp2_b[0]; s_amp = amp[0]; }
    __syncthreads();

    // ---- warp/lane geometry: each warp owns 16 consecutive points ----
    int lane = tid & 31;
    int g = lane >> 2;            // row group 0..7
    int m = lane & 3;             // col sub-owner
    int wbase = (blockIdx.x * 8 + (tid >> 5)) * 16;   // first point idx of warp
    int b = wbase / NP;                                // uniform per warp (16 | 20000)
    int p0 = wbase + g, p1 = wbase + g + 8;

    float P0x = pos[3*(p0 - b*NP) + 0], P0y = pos[3*(p0 - b*NP) + 1], P0z = pos[3*(p0 - b*NP) + 2];
    float P1x = pos[3*(p1 - b*NP) + 0], P1y = pos[3*(p1 - b*NP) + 1], P1z = pos[3*(p1 - b*NP) + 2];

    float xf[4][4];

    // ================= amplitude head =================
    #pragma unroll
    for (int nt = 0; nt < 4; nt++) {
        int c0 = 8*nt + 2*m;
        float4 w0 = s_la1p4[c0], w1 = s_la1p4[c0+1];
        float ca0 = s_camp[b*NN + c0], ca1 = s_camp[b*NN + c0 + 1];
        xf[nt][0] = ca0 + w0.x*P0x + w0.y*P0y + w0.z*P0z;
        xf[nt][1] = ca1 + w1.x*P0x + w1.y*P0y + w1.z*P0z;
        xf[nt][2] = ca0 + w0.x*P1x + w0.y*P1y + w0.z*P1z;
        xf[nt][3] = ca1 + w1.x*P1x + w1.y*P1y + w1.z*P1z;
    }
    #pragma unroll
    for (int l = 0; l < NL; l++)
        run_layer(xf, &s_wb_hi[l*4*32], &s_wb_lo[l*4*32], &s_bias[l*NN], lane);

    float sg = 0.f, sh = 0.f;   // amp final dot partials, rows g and g+8
    #pragma unroll
    for (int nt = 0; nt < 4; nt++) {
        int c0 = 8*nt + 2*m;
        float wa = s_la2[c0], wb = s_la2[c0+1];
        sg += xf[nt][0]*wa + xf[nt][1]*wb;
        sh += xf[nt][2]*wa + xf[nt][3]*wb;
    }
    sg += __shfl_xor_sync(0xFFFFFFFF, sg, 1); sg += __shfl_xor_sync(0xFFFFFFFF, sg, 2);
    sh += __shfl_xor_sync(0xFFFFFFFF, sh, 1); sh += __shfl_xor_sync(0xFFFFFFFF, sh, 2);

    // ================= deform head =================
    float t0g = 0.f, t1g = 0.f, t2g = 0.f, t0h = 0.f, t1h = 0.f, t2h = 0.f;
    if (dflag > 0) {
        #pragma unroll
        for (int nt = 0; nt < 4; nt++) {
            int c0 = 8*nt + 2*m;
            float4 w0 = s_l0p4[c0], w1 = s_l0p4[c0+1];
            float cd0 = s_cdef[b*NN + c0], cd1 = s_cdef[b*NN + c0 + 1];
            xf[nt][0] = cd0 + w0.x*P0x + w0.y*P0y + w0.z*P0z;
            xf[nt][1] = cd1 + w1.x*P0x + w1.y*P0y + w1.z*P0z;
            xf[nt][2] = cd0 + w0.x*P1x + w0.y*P1y + w0.z*P1z;
            xf[nt][3] = cd1 + w1.x*P1x + w1.y*P1y + w1.z*P1z;
        }
        #pragma unroll
        for (int l = 0; l < NL; l++)
            run_layer(xf, &s_wb_hi[(3+l)*4*32], &s_wb_lo[(3+l)*4*32], &s_bias[(3+l)*NN], lane);

        #pragma unroll
        for (int nt = 0; nt < 4; nt++) {
            int c0 = 8*nt + 2*m;
            float4 wa = s_l1a4[c0], wb = s_l1a4[c0+1];
            t0g += xf[nt][0]*wa.x + xf[nt][1]*wb.x;
            t1g += xf[nt][0]*wa.y + xf[nt][1]*wb.y;
            t2g += xf[nt][0]*wa.z + xf[nt][1]*wb.z;
            t0h += xf[nt][2]*wa.x + xf[nt][3]*wb.x;
            t1h += xf[nt][2]*wa.y + xf[nt][3]*wb.y;
            t2h += xf[nt][2]*wa.z + xf[nt][3]*wb.z;
        }
        t0g += __shfl_xor_sync(0xFFFFFFFF, t0g, 1); t0g += __shfl_xor_sync(0xFFFFFFFF, t0g, 2);
        t1g += __shfl_xor_sync(0xFFFFFFFF, t1g, 1); t1g += __shfl_xor_sync(0xFFFFFFFF, t1g, 2);
        t2g += __shfl_xor_sync(0xFFFFFFFF, t2g, 1); t2g += __shfl_xor_sync(0xFFFFFFFF, t2g, 2);
        t0h += __shfl_xor_sync(0xFFFFFFFF, t0h, 1); t0h += __shfl_xor_sync(0xFFFFFFFF, t0h, 2);
        t1h += __shfl_xor_sync(0xFFFFFFFF, t1h, 1); t1h += __shfl_xor_sync(0xFFFFFFFF, t1h, 2);
        t2h += __shfl_xor_sync(0xFFFFFFFF, t2h, 1); t2h += __shfl_xor_sync(0xFFFFFFFF, t2h, 2);
    }

    // ================= per-point epilogue (m=0 -> row g, m=1 -> row g+8) =================
    if (m < 2) {
        int idx = (m == 0) ? p0 : p1;
        float px = (m == 0) ? P0x : P1x;
        float py = (m == 0) ? P0y : P1y;
        float pz = (m == 0) ? P0z : P1z;
        float sacc = ((m == 0) ? sg : sh) + s_la2b;
        float amp_corr = sigmoid_fast(sacc);

        float res0 = 0.f, res1 = 0.f, res2 = 0.f;
        if (dflag > 0) {
            float t0 = (m == 0) ? t0g : t0h;
            float t1 = (m == 0) ? t1g : t1h;
            float t2 = (m == 0) ? t2g : t2h;
            t0 = tanh_fast(t0); t1 = tanh_fast(t1); t2 = tanh_fast(t2);
            res0 = t0*s_l1b[0] + t1*s_l1b[1] + t2*s_l1b[2];
            res1 = t0*s_l1b[3] + t1*s_l1b[4] + t2*s_l1b[5];
            res2 = t0*s_l1b[6] + t1*s_l1b[7] + t2*s_l1b[8];
        }
        float pd0 = px + res0, pd1 = py + res1, pd2 = pz + res2;

        out[OFF_AC + idx] = amp_corr;
        out[OFF_RES + 3*idx + 0] = res0;
        out[OFF_RES + 3*idx + 1] = res1;
        out[OFF_RES + 3*idx + 2] = res2;
        out[OFF_PD + 3*idx + 0] = pd0;
        out[OFF_PD + 3*idx + 1] = pd1;
        out[OFF_PD + 3*idx + 2] = pd2;

        const float* rb = &s_r[b*9];
        float proj0 = rb[0]*pd0 + rb[1]*pd1 + rb[2]*pd2;
        float proj1 = rb[3]*pd0 + rb[4]*pd1 + rb[5]*pd2;

        float A = s_amp * amp_corr;
        float fcx = rintf((proj0 + 0.5f) * (float)(BOX - 1));   // round-half-even = jnp.round
        float fcy = rintf((proj1 + 0.5f) * (float)(BOX - 1));

        if (fcx >= (float)(-HALF) && fcx <= (float)(BOX - 1 + HALF) &&
            fcy >= (float)(-HALF) && fcy <= (float)(BOX - 1 + HALF)) {
            int cx = (int)fcx, cy = (int)fcy;
            atomicAdd(&g_tmp[((size_t)b*TDIM + (cy + HALF))*TDIM + (cx + HALF)], A);
        }
    }
}

// Dense separable 9x9 conv over padded point-mass buffer (512 threads, float4 loads).
// out[b][y][x] = sum_jy ky[jy] * sum_jx kx[jx] * tmp[b][y+8-jy][x+8-jx]
// where kx[j] = k2[4][j], ky[j] = k2[j][4]/k2[4][4]  (exact outer-product factorization)
__global__ void __launch_bounds__(512) conv_sep_kernel(const float* __restrict__ k2,
                                                       float* __restrict__ out)
{
    __shared__ __align__(16) float s_in[72][72];    // 64+8 halo in both dims
    __shared__ float s_mid[72][64];

    int bt  = blockIdx.x;             // 16 batches x 4x4 tiles = 256 blocks
    int b   = bt >> 4;
    int ty0 = ((bt >> 2) & 3) * 64;
    int tx0 = (bt & 3) * 64;
    int tid = threadIdx.x;

    float inv_c = 1.f / k2[HALF*KS + HALF];
    float kx[KS], ky[KS];
    #pragma unroll
    for (int j = 0; j < KS; j++) { kx[j] = k2[HALF*KS + j]; ky[j] = k2[j*KS + HALF] * inv_c; }

    // float4 tile load: 72 rows x 18 float4 (alignment: TDIM*4 and tx0*4 are 16B multiples)
    const float4* base4 = (const float4*)(g_tmp + ((size_t)b*TDIM + ty0)*TDIM + tx0);
    for (int i = tid; i < 72*18; i += 512) {
        int rr = i / 18, cc4 = i % 18;
        ((float4*)&s_in[rr][0])[cc4] = base4[rr*(TDIM/4) + cc4];
    }
    __syncthreads();

    for (int i = tid; i < 72*64; i += 512) {
        int rr = i >> 6, x = i & 63;
        float a = 0.f;
        #pragma unroll
        for (int jx = 0; jx < KS; jx++) a += kx[jx] * s_in[rr][x + 2*HALF - jx];
        s_mid[rr][x] = a;
    }
    __syncthreads();

    for (int i = tid; i < 64*64; i += 512) {
        int y = i >> 6, x = i & 63;
        float a = 0.f;
        #pragma unroll
        for (int jy = 0; jy < KS; jy++) a += ky[jy] * s_mid[y + 2*HALF - jy][x];
        out[((size_t)b*BOX + ty0 + y)*BOX + tx0 + x] = a;
    }
}

extern "C" void kernel_launch(void* const* d_in, const int* in_sizes, int n_in,
                              void* d_out, int out_size)
{
    const float* z          = (const float*)d_in[0];
    const float* r          = (const float*)d_in[1];
    const float* pos        = (const float*)d_in[2];
    const float* amp        = (const float*)d_in[3];
    const float* linamp1_W  = (const float*)d_in[4];
    const float* ampblock_W = (const float*)d_in[5];
    const float* ampblock_b = (const float*)d_in[6];
    const float* linamp2_W  = (const float*)d_in[7];
    const float* linamp2_b  = (const float*)d_in[8];
    const float* lin0_W     = (const float*)d_in[9];
    const float* deform_W   = (const float*)d_in[10];
    const float* deform_b   = (const float*)d_in[11];
    const float* lin1a_W    = (const float*)d_in[12];
    const float* lin1b_W    = (const float*)d_in[13];
    const float* k2         = (const float*)d_in[14];
    const int*   dptr       = (const int*)d_in[15];
    float* out = (float*)d_out;

    setup_kernel<<<ZERO_BLOCKS, 256>>>(z, linamp1_W, ampblock_W, deform_W, lin0_W);
    fused_decoder_kernel<<<(NB*NP)/128, 256>>>(     // 2500 blocks: 8 warps x 16 points
        r, pos, amp, linamp1_W, ampblock_b, linamp2_W, linamp2_b,
        lin0_W, deform_b, lin1a_W, lin1b_W, dptr, out);
    conv_sep_kernel<<<256, 512>>>(k2, out);
}